// round 16
// baseline (speedup 1.0000x reference)
#include <cuda_runtime.h>
#include <cuda_fp16.h>
#include <cstdint>
#include <math.h>

#define EMBED   1024
#define SEQ     1024
#define BATCH   8
#define NTOK    8192
#define HIDDEN  4096
#define HEADS   16
#define HDIM    64
#define QKV3    3072

// ---------------- scratch (no cudaMalloc allowed) ----------------
__device__ __half g_ln    [NTOK * EMBED];
__device__ __half g_qkv   [(size_t)NTOK * QKV3];
__device__ __half g_y     [NTOK * EMBED];
__device__ float  g_x1    [NTOK * EMBED];
__device__ __half g_h     [(size_t)NTOK * HIDDEN];
__device__ __half g_wqkvT [(size_t)QKV3 * EMBED];
__device__ __half g_woutT [(size_t)EMBED * EMBED];
__device__ __half g_wupT  [(size_t)HIDDEN * EMBED];
__device__ __half g_wdownT[(size_t)EMBED * HIDDEN];

// Aux stream/events, created once at static-init time.
struct AuxRes {
    cudaStream_t s2;
    cudaEvent_t evf, evj;
    AuxRes() {
        cudaStreamCreateWithFlags(&s2, cudaStreamNonBlocking);
        cudaEventCreateWithFlags(&evf, cudaEventDisableTiming);
        cudaEventCreateWithFlags(&evj, cudaEventDisableTiming);
    }
};
static AuxRes g_aux;

// ---------------- helpers ----------------
__device__ __forceinline__ uint32_t smem_u32(const void* p) {
    uint32_t a;
    asm("{ .reg .u64 t; cvta.to.shared.u64 t, %1; cvt.u32.u64 %0, t; }" : "=r"(a) : "l"(p));
    return a;
}
__device__ __forceinline__ void cp_async16(uint32_t dst, const void* src) {
    asm volatile("cp.async.cg.shared.global [%0], [%1], 16;" :: "r"(dst), "l"(src) : "memory");
}
#define CP_COMMIT() asm volatile("cp.async.commit_group;" ::: "memory")
template <int N>
__device__ __forceinline__ void cp_wait() {
    asm volatile("cp.async.wait_group %0;" :: "n"(N) : "memory");
}
__device__ __forceinline__ float exp2_fast(float x) {
    float y;
    asm("ex2.approx.ftz.f32 %0, %1;" : "=f"(y) : "f"(x));
    return y;
}

// m16n8k16 fp16 mma, fp32 accumulate (sm_80+ portable PTX)
__device__ __forceinline__ void mma_f16(float* c, const uint32_t* a, const uint32_t* b) {
    asm volatile(
        "mma.sync.aligned.m16n8k16.row.col.f32.f16.f16.f32 "
        "{%0,%1,%2,%3}, {%4,%5,%6,%7}, {%8,%9}, {%0,%1,%2,%3};"
        : "+f"(c[0]), "+f"(c[1]), "+f"(c[2]), "+f"(c[3])
        : "r"(a[0]), "r"(a[1]), "r"(a[2]), "r"(a[3]), "r"(b[0]), "r"(b[1]));
}

__device__ __forceinline__ void ldmatrix_x4(uint32_t& r0, uint32_t& r1,
                                            uint32_t& r2, uint32_t& r3,
                                            uint32_t addr) {
    asm volatile("ldmatrix.sync.aligned.m8n8.x4.shared.b16 {%0,%1,%2,%3}, [%4];"
                 : "=r"(r0), "=r"(r1), "=r"(r2), "=r"(r3) : "r"(addr));
}
__device__ __forceinline__ void ldmatrix_x4_trans(uint32_t& r0, uint32_t& r1,
                                                  uint32_t& r2, uint32_t& r3,
                                                  uint32_t addr) {
    asm volatile("ldmatrix.sync.aligned.m8n8.x4.trans.shared.b16 {%0,%1,%2,%3}, [%4];"
                 : "=r"(r0), "=r"(r1), "=r"(r2), "=r"(r3) : "r"(addr));
}

#define SOFTMAX_C 0.18033688011112042f   // 0.125 * log2(e)

// ---------------- fp16 tensor-core GEMM (at HMMA-issue ceiling) ----
#define BM 128
#define BN 256
#define BKH 64
#define PH 72
#define PW 36
#define A_WORDS (BM * PW)
#define B_WORDS (BN * PW)
#define STAGE_WORDS (A_WORDS + B_WORDS)
#define NSTAGE 4
#define SMEM_DYN (NSTAGE * STAGE_WORDS * 4)   // 221184 bytes

template<bool RELU, bool RES, bool OUTH, bool SCALEQ>
__global__ void __launch_bounds__(256, 1)
gemm_mma(const __half* __restrict__ A, const __half* __restrict__ Bt,
         const float* __restrict__ bias, const float* __restrict__ res,
         void* __restrict__ Cv, int N, int K)
{
    extern __shared__ uint32_t smw[];
    const uint32_t sbase = smem_u32(smw);
    const int tid  = threadIdx.x;
    const int wid  = tid >> 5, lane = tid & 31;
    const int gq   = lane >> 2, tq = lane & 3;
    const int wm   = wid >> 2,  wn = wid & 3;
    const int m0   = blockIdx.y * BM, n0 = blockIdx.x * BN;
    const int nk   = K / BKH;

    float acc[4][8][4];
    #pragma unroll
    for (int i = 0; i < 4; i++)
        #pragma unroll
        for (int j = 0; j < 8; j++)
            #pragma unroll
            for (int q = 0; q < 4; q++) acc[i][j][q] = 0.f;

    const __half* Ag0 = A  + (size_t)m0 * K;
    const __half* Bg0 = Bt + (size_t)n0 * K;

    auto load_stage = [&](int s, int kt) {
        uint32_t sa = sbase + (uint32_t)s * (STAGE_WORDS * 4);
        const __half* Ag = Ag0 + kt * BKH;
        #pragma unroll
        for (int j = 0; j < 4; j++) {
            int c = tid + j * 256;
            int row = c >> 3, kc = c & 7;
            cp_async16(sa + (uint32_t)(row * 144 + kc * 16),
                       Ag + (size_t)row * K + kc * 8);
        }
        uint32_t sb = sa + A_WORDS * 4;
        const __half* Bg = Bg0 + kt * BKH;
        #pragma unroll
        for (int j = 0; j < 8; j++) {
            int c = tid + j * 256;
            int row = c >> 3, kc = c & 7;
            cp_async16(sb + (uint32_t)(row * 144 + kc * 16),
                       Bg + (size_t)row * K + kc * 8);
        }
        CP_COMMIT();
    };

    load_stage(0, 0);
    load_stage(1, 1);
    load_stage(2, 2);

    for (int kt = 0; kt < nk; kt++) {
        if (kt + 2 < nk) cp_wait<2>();
        else if (kt + 1 < nk) cp_wait<1>();
        else cp_wait<0>();
        __syncthreads();
        // Single barrier per iteration: the prefetch below targets buffer
        // (kt+3)%4, last read at iter kt-1; all warps passing the barrier
        // above have finished iter kt-1's MMAs.
        if (kt + 3 < nk) load_stage((kt + 3) % NSTAGE, kt + 3);

        const uint32_t* a_s = smw + (kt % NSTAGE) * STAGE_WORDS;
        const uint32_t* b_s = a_s + A_WORDS;

        #pragma unroll
        for (int s = 0; s < 4; s++) {
            const int k8w = s * 8;
            uint32_t af[4][4];
            #pragma unroll
            for (int mi = 0; mi < 4; mi++) {
                int rb = wm * 64 + mi * 16;
                af[mi][0] = a_s[(rb + gq)     * PW + k8w + tq];
                af[mi][1] = a_s[(rb + gq + 8) * PW + k8w + tq];
                af[mi][2] = a_s[(rb + gq)     * PW + k8w + tq + 4];
                af[mi][3] = a_s[(rb + gq + 8) * PW + k8w + tq + 4];
            }
            uint32_t bf[8][2];
            #pragma unroll
            for (int ni = 0; ni < 8; ni++) {
                int nb = wn * 64 + ni * 8;
                bf[ni][0] = b_s[(nb + gq) * PW + k8w + tq];
                bf[ni][1] = b_s[(nb + gq) * PW + k8w + tq + 4];
            }
            #pragma unroll
            for (int mi = 0; mi < 4; mi++)
                #pragma unroll
                for (int ni = 0; ni < 8; ni++)
                    mma_f16(acc[mi][ni], af[mi], bf[ni]);
        }
    }

    // ---------- epilogue ----------
    const float qs = (SCALEQ && n0 < EMBED) ? SOFTMAX_C : 1.0f;
    float*  Cf = (float*)Cv;
    __half* Ch = (__half*)Cv;
    #pragma unroll
    for (int ni = 0; ni < 8; ni++) {
        int col = n0 + wn * 64 + ni * 8 + 2 * tq;
        float2 bv = __ldg((const float2*)(bias + col));
        #pragma unroll
        for (int mi = 0; mi < 4; mi++) {
            int row = m0 + wm * 64 + mi * 16 + gq;
            float2 v0, v1;
            v0.x = acc[mi][ni][0] + bv.x;
            v0.y = acc[mi][ni][1] + bv.y;
            v1.x = acc[mi][ni][2] + bv.x;
            v1.y = acc[mi][ni][3] + bv.y;
            if (RES) {
                float2 r0 = __ldg((const float2*)(res + (size_t)row * N + col));
                float2 r1 = __ldg((const float2*)(res + (size_t)(row + 8) * N + col));
                v0.x += r0.x; v0.y += r0.y;
                v1.x += r1.x; v1.y += r1.y;
            }
            if (RELU) {
                v0.x = fmaxf(v0.x, 0.f); v0.y = fmaxf(v0.y, 0.f);
                v1.x = fmaxf(v1.x, 0.f); v1.y = fmaxf(v1.y, 0.f);
            }
            if (SCALEQ) {
                v0.x *= qs; v0.y *= qs;
                v1.x *= qs; v1.y *= qs;
            }
            if (OUTH) {
                *(__half2*)(Ch + (size_t)row * N + col)       = __floats2half2_rn(v0.x, v0.y);
                *(__half2*)(Ch + (size_t)(row + 8) * N + col) = __floats2half2_rn(v1.x, v1.y);
            } else {
                *(float2*)(Cf + (size_t)row * N + col)       = v0;
                *(float2*)(Cf + (size_t)(row + 8) * N + col) = v1;
            }
        }
    }
}

// ---------------- weight transpose + fp16 round: in[K,N] -> out[N,K] ------
__global__ void transpose_h(const float* __restrict__ in, __half* __restrict__ out,
                            int K, int N)
{
    __shared__ float t[32][33];
    int n  = blockIdx.x * 32 + threadIdx.x;
    int k0 = blockIdx.y * 32;
    #pragma unroll
    for (int r = 0; r < 32; r += 8)
        t[threadIdx.y + r][threadIdx.x] = in[(size_t)(k0 + threadIdx.y + r) * N + n];
    __syncthreads();
    int k   = k0 + threadIdx.x;
    int nn0 = blockIdx.x * 32;
    #pragma unroll
    for (int r = 0; r < 32; r += 8)
        out[(size_t)(nn0 + threadIdx.y + r) * K + k] = __float2half_rn(t[threadIdx.x][threadIdx.y + r]);
}

// ---------------- LayerNorm (fp16 output; feeds GEMMs only) ------
__global__ void ln_kernel(const float* __restrict__ x,
                          const float* __restrict__ g,
                          const float* __restrict__ b,
                          __half* __restrict__ out)
{
    int row = blockIdx.x;
    int t   = threadIdx.x;
    const float4* xr = (const float4*)(x + (size_t)row * EMBED);
    float4 v = xr[t];

    float s  = v.x + v.y + v.z + v.w;
    float s2 = v.x*v.x + v.y*v.y + v.z*v.z + v.w*v.w;
    #pragma unroll
    for (int off = 16; off > 0; off >>= 1) {
        s  += __shfl_xor_sync(0xffffffffu, s,  off);
        s2 += __shfl_xor_sync(0xffffffffu, s2, off);
    }
    __shared__ float red1[8], red2[8];
    int wid = t >> 5, lane = t & 31;
    if (lane == 0) { red1[wid] = s; red2[wid] = s2; }
    __syncthreads();
    __shared__ float s_mu, s_rstd;
    if (t == 0) {
        float ts = 0.f, ts2 = 0.f;
        #pragma unroll
        for (int i = 0; i < 8; i++) { ts += red1[i]; ts2 += red2[i]; }
        float mu  = ts * (1.0f / EMBED);
        float var = ts2 * (1.0f / EMBED) - mu * mu;
        s_mu = mu; s_rstd = rsqrtf(var + 1e-5f);
    }
    __syncthreads();
    float mu = s_mu, rstd = s_rstd;

    float4 gv = ((const float4*)g)[t];
    float4 bv = ((const float4*)b)[t];
    __half2* orow = (__half2*)(out + (size_t)row * EMBED);
    orow[2 * t]     = __floats2half2_rn((v.x - mu) * rstd * gv.x + bv.x,
                                        (v.y - mu) * rstd * gv.y + bv.y);
    orow[2 * t + 1] = __floats2half2_rn((v.z - mu) * rstd * gv.z + bv.z,
                                        (v.w - mu) * rstd * gv.w + bv.w);
}

// ---------------- flash attention via fp16 mma.sync ----------------
// BQ=256 per CTA, 8 warps (32 q-rows each: 2 x m16), BK=64, D=64,
// KV double-buffered. Halves KV L2 traffic + per-CTA prologue count vs BQ=128.
// P stays in registers (S C-frag == P@V A-frag). K B-frags via ldmatrix.x4.
// q pre-scaled by SOFTMAX_C at qkv epilogue -> S is already in exp2 domain.
#define AQW 0                       // word offsets: Q 256x36 = 9216 words
#define AKW(b) (9216 + (b) * 2304)
#define AVW(b) (13824 + (b) * 2304)
#define ATT_SMEM (18432 * 4)        // 73728 bytes

__global__ void __launch_bounds__(256, 1)
attn_mma(const __half* __restrict__ qkv, __half* __restrict__ y)
{
    extern __shared__ uint32_t smw[];
    const uint32_t sbase = smem_u32(smw);

    const int qt = blockIdx.x, h = blockIdx.y, b = blockIdx.z;
    const int tid = threadIdx.x, wid = tid >> 5, lane = tid & 31;
    const int gq = lane >> 2, tq = lane & 3;
    const int rb0 = wid * 32;        // 8 warps x 32 q-rows = 256

    const __half* qbase = qkv + ((size_t)b * SEQ + qt * 256) * QKV3 + h * HDIM;
    const __half* kbase = qkv + (size_t)b * SEQ * QKV3 + EMBED + h * HDIM;
    const __half* vbase = kbase + EMBED;

    // Q tile: 256 rows x 8 chunks(16B) = 2048 chunks; 8 per thread (256 thr)
    #pragma unroll
    for (int j = 0; j < 8; j++) {
        int c = tid + j * 256;
        int row = c >> 3, kc = c & 7;
        cp_async16(sbase + AQW * 4 + (uint32_t)(row * 144 + kc * 16),
                   qbase + (size_t)row * QKV3 + kc * 8);
    }
    // KV tile 0: 64 rows x 8 chunks each = 512 chunks; 2 per thread each
    #pragma unroll
    for (int j = 0; j < 2; j++) {
        int c = tid + j * 256;
        int row = c >> 3, kc = c & 7;
        cp_async16(sbase + AKW(0) * 4 + (uint32_t)(row * 144 + kc * 16),
                   kbase + (size_t)row * QKV3 + kc * 8);
        cp_async16(sbase + AVW(0) * 4 + (uint32_t)(row * 144 + kc * 16),
                   vbase + (size_t)row * QKV3 + kc * 8);
    }
    CP_COMMIT();

    float o[2][8][4];
    float mrow[2][2], lrow[2][2];
    #pragma unroll
    for (int mi = 0; mi < 2; mi++) {
        mrow[mi][0] = mrow[mi][1] = -1e30f;
        lrow[mi][0] = lrow[mi][1] = 0.f;
        #pragma unroll
        for (int ni = 0; ni < 8; ni++)
            #pragma unroll
            for (int q = 0; q < 4; q++) o[mi][ni][q] = 0.f;
    }

    cp_wait<0>();
    __syncthreads();

    // hoist Q fragments (loop-invariant)
    uint32_t aq[4][2][4];
    {
        const uint32_t* q_s = smw + AQW;
        #pragma unroll
        for (int ks = 0; ks < 4; ks++) {
            const int k8w = ks * 8;
            #pragma unroll
            for (int mi = 0; mi < 2; mi++) {
                int rb = rb0 + mi * 16;
                aq[ks][mi][0] = q_s[(rb + gq)     * PW + k8w + tq];
                aq[ks][mi][1] = q_s[(rb + gq + 8) * PW + k8w + tq];
                aq[ks][mi][2] = q_s[(rb + gq)     * PW + k8w + tq + 4];
                aq[ks][mi][3] = q_s[(rb + gq + 8) * PW + k8w + tq + 4];
            }
        }
    }

    // ldmatrix lane->address components
    const int krow = ((lane >> 4) & 1) * 8 + (lane & 7);
    const int kwof = ((lane >> 3) & 1) * 4;
    const int vrow = ((lane >> 3) & 1) * 8 + (lane & 7);
    const int vcol = (lane >> 4) * 8;

    const int NT = SEQ / 64;
    for (int kt = 0; kt < NT; kt++) {
        const int cur = kt & 1;
        if (kt > 0) {
            cp_wait<0>();      // data for buf cur arrived
            __syncthreads();   // and all warps done reading buf cur^1
        }
        if (kt + 1 < NT) {
            const int nxt = cur ^ 1;
            #pragma unroll
            for (int j = 0; j < 2; j++) {
                int c = tid + j * 256;
                int row = c >> 3, kc = c & 7;
                cp_async16(sbase + AKW(nxt) * 4 + (uint32_t)(row * 144 + kc * 16),
                           kbase + (size_t)((kt + 1) * 64 + row) * QKV3 + kc * 8);
                cp_async16(sbase + AVW(nxt) * 4 + (uint32_t)(row * 144 + kc * 16),
                           vbase + (size_t)((kt + 1) * 64 + row) * QKV3 + kc * 8);
            }
            CP_COMMIT();
        }

        const uint32_t kb = sbase + AKW(cur) * 4;

        // ---- S = Q @ K^T  (4 k16 steps over D=64; q carries 0.125*log2e) ----
        float s[2][8][4];
        #pragma unroll
        for (int mi = 0; mi < 2; mi++)
            #pragma unroll
            for (int ni = 0; ni < 8; ni++)
                #pragma unroll
                for (int q = 0; q < 4; q++) s[mi][ni][q] = 0.f;

        #pragma unroll
        for (int ks = 0; ks < 4; ks++) {
            const int k8w = ks * 8;
            uint32_t bk[8][2];
            #pragma unroll
            for (int j = 0; j < 4; j++) {
                uint32_t addr = kb + (uint32_t)(((16 * j + krow) * PW) + k8w + kwof) * 4;
                ldmatrix_x4(bk[2 * j][0], bk[2 * j][1],
                            bk[2 * j + 1][0], bk[2 * j + 1][1], addr);
            }
            #pragma unroll
            for (int mi = 0; mi < 2; mi++)
                #pragma unroll
                for (int ni = 0; ni < 8; ni++)
                    mma_f16(s[mi][ni], aq[ks][mi], bk[ni]);
        }

        // ---- online softmax (exp2 domain); P packed into A-fragment regs ----
        uint32_t ph[2][8][2];
        #pragma unroll
        for (int mi = 0; mi < 2; mi++) {
            float rm0 = -1e30f, rm1 = -1e30f;
            #pragma unroll
            for (int ni = 0; ni < 8; ni++) {
                rm0 = fmaxf(rm0, fmaxf(s[mi][ni][0], s[mi][ni][1]));
                rm1 = fmaxf(rm1, fmaxf(s[mi][ni][2], s[mi][ni][3]));
            }
            rm0 = fmaxf(rm0, __shfl_xor_sync(0xffffffffu, rm0, 1));
            rm0 = fmaxf(rm0, __shfl_xor_sync(0xffffffffu, rm0, 2));
            rm1 = fmaxf(rm1, __shfl_xor_sync(0xffffffffu, rm1, 1));
            rm1 = fmaxf(rm1, __shfl_xor_sync(0xffffffffu, rm1, 2));

            float mn0 = fmaxf(mrow[mi][0], rm0);
            float mn1 = fmaxf(mrow[mi][1], rm1);
            float a0 = exp2_fast(mrow[mi][0] - mn0);
            float a1 = exp2_fast(mrow[mi][1] - mn1);
            mrow[mi][0] = mn0; mrow[mi][1] = mn1;

            float sum0 = 0.f, sum1 = 0.f;
            #pragma unroll
            for (int ni = 0; ni < 8; ni++) {
                float p0 = exp2_fast(s[mi][ni][0] - mn0);
                float p1 = exp2_fast(s[mi][ni][1] - mn0);
                float p2 = exp2_fast(s[mi][ni][2] - mn1);
                float p3 = exp2_fast(s[mi][ni][3] - mn1);
                sum0 += p0 + p1;
                sum1 += p2 + p3;
                __half2 hp0 = __floats2half2_rn(p0, p1);
                __half2 hp1 = __floats2half2_rn(p2, p3);
                ph[mi][ni][0] = *(uint32_t*)&hp0;
                ph[mi][ni][1] = *(uint32_t*)&hp1;
                o[mi][ni][0] *= a0; o[mi][ni][1] *= a0;
                o[mi][ni][2] *= a1; o[mi][ni][3] *= a1;
            }
            sum0 += __shfl_xor_sync(0xffffffffu, sum0, 1);
            sum0 += __shfl_xor_sync(0xffffffffu, sum0, 2);
            sum1 += __shfl_xor_sync(0xffffffffu, sum1, 1);
            sum1 += __shfl_xor_sync(0xffffffffu, sum1, 2);
            lrow[mi][0] = lrow[mi][0] * a0 + sum0;
            lrow[mi][1] = lrow[mi][1] * a1 + sum1;
        }

        // ---- O += P @ V  (P A-frags straight from registers) ----
        const uint32_t vb = sbase + AVW(cur) * 4;
        #pragma unroll
        for (int ks = 0; ks < 4; ks++) {
            uint32_t ap[2][4];
            #pragma unroll
            for (int mi = 0; mi < 2; mi++) {
                ap[mi][0] = ph[mi][2 * ks][0];
                ap[mi][1] = ph[mi][2 * ks][1];
                ap[mi][2] = ph[mi][2 * ks + 1][0];
                ap[mi][3] = ph[mi][2 * ks + 1][1];
            }
            uint32_t bv[8][2];
            #pragma unroll
            for (int j = 0; j < 4; j++) {
                uint32_t addr = vb + (uint32_t)(((ks * 16 + vrow) * PH) + j * 16 + vcol) * 2;
                ldmatrix_x4_trans(bv[2 * j][0], bv[2 * j][1],
                                  bv[2 * j + 1][0], bv[2 * j + 1][1], addr);
            }
            #pragma unroll
            for (int mi = 0; mi < 2; mi++)
                #pragma unroll
                for (int ni = 0; ni < 8; ni++)
                    mma_f16(o[mi][ni], ap[mi], bv[ni]);
        }
    }

    // ---- write y (fp16; feeds out-proj GEMM) ----
    #pragma unroll
    for (int mi = 0; mi < 2; mi++) {
        float inv0 = 1.0f / lrow[mi][0];
        float inv1 = 1.0f / lrow[mi][1];
        int r0 = qt * 256 + rb0 + mi * 16 + gq;
        #pragma unroll
        for (int ni = 0; ni < 8; ni++) {
            int col = h * HDIM + ni * 8 + 2 * tq;
            *(__half2*)(y + ((size_t)b * SEQ + r0) * EMBED + col) =
                __floats2half2_rn(o[mi][ni][0] * inv0, o[mi][ni][1] * inv0);
            *(__half2*)(y + ((size_t)b * SEQ + r0 + 8) * EMBED + col) =
                __floats2half2_rn(o[mi][ni][2] * inv1, o[mi][ni][3] * inv1);
        }
    }
}

// ---------------- launch (round-10/12 topology: known good) ----------------
extern "C" void kernel_launch(void* const* d_in, const int* in_sizes, int n_in,
                              void* d_out, int out_size)
{
    (void)in_sizes; (void)n_in; (void)out_size;
    const float* x      = (const float*)d_in[0];
    const float* ln1_g  = (const float*)d_in[1];
    const float* ln1_b  = (const float*)d_in[2];
    const float* w_qkv  = (const float*)d_in[3];
    const float* b_qkv  = (const float*)d_in[4];
    const float* w_out  = (const float*)d_in[5];
    const float* b_out  = (const float*)d_in[6];
    const float* ln2_g  = (const float*)d_in[7];
    const float* ln2_b  = (const float*)d_in[8];
    const float* w_up   = (const float*)d_in[9];
    const float* b_up   = (const float*)d_in[10];
    const float* w_down = (const float*)d_in[11];
    const float* b_down = (const float*)d_in[12];
    float* out = (float*)d_out;

    __half *p_ln, *p_qkv, *p_y, *p_h;
    float *p_x1;
    __half *p_wqkvT, *p_woutT, *p_wupT, *p_wdownT;
    cudaGetSymbolAddress((void**)&p_ln,     g_ln);
    cudaGetSymbolAddress((void**)&p_qkv,    g_qkv);
    cudaGetSymbolAddress((void**)&p_y,      g_y);
    cudaGetSymbolAddress((void**)&p_x1,     g_x1);
    cudaGetSymbolAddress((void**)&p_h,      g_h);
    cudaGetSymbolAddress((void**)&p_wqkvT,  g_wqkvT);
    cudaGetSymbolAddress((void**)&p_woutT,  g_woutT);
    cudaGetSymbolAddress((void**)&p_wupT,   g_wupT);
    cudaGetSymbolAddress((void**)&p_wdownT, g_wdownT);

    cudaFuncSetAttribute(gemm_mma<false, false, true, true>,
                         cudaFuncAttributeMaxDynamicSharedMemorySize, SMEM_DYN);
    cudaFuncSetAttribute(gemm_mma<false, true, false, false>,
                         cudaFuncAttributeMaxDynamicSharedMemorySize, SMEM_DYN);
    cudaFuncSetAttribute(gemm_mma<true, false, true, false>,
                         cudaFuncAttributeMaxDynamicSharedMemorySize, SMEM_DYN);
    cudaFuncSetAttribute(attn_mma,
                         cudaFuncAttributeMaxDynamicSharedMemorySize, ATT_SMEM);

    dim3 tb(32, 8);
    // 1) w_qkv transpose (needed by qkv GEMM) — main stream
    transpose_h<<<dim3(QKV3 / 32, EMBED / 32),  tb>>>(w_qkv,  p_wqkvT,  EMBED, QKV3);
    // 2) ln1 (fp16 out)
    ln_kernel<<<NTOK, 256>>>(x, ln1_g, ln1_b, p_ln);

    // fork: remaining weight transposes run concurrently with qkv GEMM + attention
    cudaEventRecord(g_aux.evf, 0);
    cudaStreamWaitEvent(g_aux.s2, g_aux.evf, 0);
    transpose_h<<<dim3(EMBED / 32, EMBED / 32), tb, 0, g_aux.s2>>>(w_out,  p_woutT,  EMBED, EMBED);
    transpose_h<<<dim3(HIDDEN / 32, EMBED / 32),tb, 0, g_aux.s2>>>(w_up,   p_wupT,   EMBED, HIDDEN);
    transpose_h<<<dim3(EMBED / 32, HIDDEN / 32),tb, 0, g_aux.s2>>>(w_down, p_wdownT, HIDDEN, EMBED);
    cudaEventRecord(g_aux.evj, g_aux.s2);

    // qkv = ln1 @ w_qkv + b_qkv  (fp16 out; q columns pre-scaled by SOFTMAX_C)
    gemm_mma<false, false, true, true><<<dim3(QKV3 / BN, NTOK / BM), 256, SMEM_DYN>>>(
        p_ln, p_wqkvT, b_qkv, nullptr, p_qkv, QKV3, EMBED);
    // attention (fp16 mma; BQ=256, 8 warps; y fp16)
    attn_mma<<<dim3(SEQ / 256, HEADS, BATCH), 256, ATT_SMEM>>>(p_qkv, p_y);

    // join: transposed weights must be ready before out-proj / up / down
    cudaStreamWaitEvent(0, g_aux.evj, 0);

    // x1 = x + y @ w_out + b_out  (fp32 out)
    gemm_mma<false, true, false, false><<<dim3(EMBED / BN, NTOK / BM), 256, SMEM_DYN>>>(
        p_y, p_woutT, b_out, x, p_x1, EMBED, EMBED);
    // ln2 (fp16 out)
    ln_kernel<<<NTOK, 256>>>(p_x1, ln2_g, ln2_b, p_ln);
    // h = relu(ln2 @ w_up + b_up)  (fp16 out)
    gemm_mma<true, false, true, false><<<dim3(HIDDEN / BN, NTOK / BM), 256, SMEM_DYN>>>(
        p_ln, p_wupT, b_up, nullptr, p_h, HIDDEN, EMBED);
    // out = x1 + h @ w_down + b_down  (fp32 out)
    gemm_mma<false, true, false, false><<<dim3(EMBED / BN, NTOK / BM), 256, SMEM_DYN>>>(
        p_h, p_wdownT, b_down, p_x1, out, EMBED, HIDDEN);
}

// round 17
// speedup vs baseline: 1.0239x; 1.0239x over previous
#include <cuda_runtime.h>
#include <cuda_fp16.h>
#include <cstdint>
#include <math.h>

#define EMBED   1024
#define SEQ     1024
#define BATCH   8
#define NTOK    8192
#define HIDDEN  4096
#define HEADS   16
#define HDIM    64
#define QKV3    3072

// ---------------- scratch (no cudaMalloc allowed) ----------------
__device__ __half g_ln    [NTOK * EMBED];
__device__ __half g_qkv   [(size_t)NTOK * QKV3];
__device__ __half g_y     [NTOK * EMBED];
__device__ float  g_x1    [NTOK * EMBED];
__device__ __half g_h     [(size_t)NTOK * HIDDEN];
__device__ __half g_wqkvT [(size_t)QKV3 * EMBED];
__device__ __half g_woutT [(size_t)EMBED * EMBED];
__device__ __half g_wupT  [(size_t)HIDDEN * EMBED];
__device__ __half g_wdownT[(size_t)EMBED * HIDDEN];

// Aux stream/events, created once at static-init time.
struct AuxRes {
    cudaStream_t s2;
    cudaEvent_t evf, evj;
    AuxRes() {
        cudaStreamCreateWithFlags(&s2, cudaStreamNonBlocking);
        cudaEventCreateWithFlags(&evf, cudaEventDisableTiming);
        cudaEventCreateWithFlags(&evj, cudaEventDisableTiming);
    }
};
static AuxRes g_aux;

// ---------------- helpers ----------------
__device__ __forceinline__ uint32_t smem_u32(const void* p) {
    uint32_t a;
    asm("{ .reg .u64 t; cvta.to.shared.u64 t, %1; cvt.u32.u64 %0, t; }" : "=r"(a) : "l"(p));
    return a;
}
__device__ __forceinline__ void cp_async16(uint32_t dst, const void* src) {
    asm volatile("cp.async.cg.shared.global [%0], [%1], 16;" :: "r"(dst), "l"(src) : "memory");
}
#define CP_COMMIT() asm volatile("cp.async.commit_group;" ::: "memory")
template <int N>
__device__ __forceinline__ void cp_wait() {
    asm volatile("cp.async.wait_group %0;" :: "n"(N) : "memory");
}
__device__ __forceinline__ float exp2_fast(float x) {
    float y;
    asm("ex2.approx.ftz.f32 %0, %1;" : "=f"(y) : "f"(x));
    return y;
}

// m16n8k16 fp16 mma, fp32 accumulate (sm_80+ portable PTX)
__device__ __forceinline__ void mma_f16(float* c, const uint32_t* a, const uint32_t* b) {
    asm volatile(
        "mma.sync.aligned.m16n8k16.row.col.f32.f16.f16.f32 "
        "{%0,%1,%2,%3}, {%4,%5,%6,%7}, {%8,%9}, {%0,%1,%2,%3};"
        : "+f"(c[0]), "+f"(c[1]), "+f"(c[2]), "+f"(c[3])
        : "r"(a[0]), "r"(a[1]), "r"(a[2]), "r"(a[3]), "r"(b[0]), "r"(b[1]));
}

__device__ __forceinline__ void ldmatrix_x4(uint32_t& r0, uint32_t& r1,
                                            uint32_t& r2, uint32_t& r3,
                                            uint32_t addr) {
    asm volatile("ldmatrix.sync.aligned.m8n8.x4.shared.b16 {%0,%1,%2,%3}, [%4];"
                 : "=r"(r0), "=r"(r1), "=r"(r2), "=r"(r3) : "r"(addr));
}
__device__ __forceinline__ void ldmatrix_x4_trans(uint32_t& r0, uint32_t& r1,
                                                  uint32_t& r2, uint32_t& r3,
                                                  uint32_t addr) {
    asm volatile("ldmatrix.sync.aligned.m8n8.x4.trans.shared.b16 {%0,%1,%2,%3}, [%4];"
                 : "=r"(r0), "=r"(r1), "=r"(r2), "=r"(r3) : "r"(addr));
}

#define SOFTMAX_C 0.18033688011112042f   // 0.125 * log2(e)

// ---------------- fp16 tensor-core GEMM (at HMMA-issue ceiling) ----
#define BM 128
#define BN 256
#define BKH 64
#define PH 72
#define PW 36
#define A_WORDS (BM * PW)
#define B_WORDS (BN * PW)
#define STAGE_WORDS (A_WORDS + B_WORDS)
#define NSTAGE 4
#define SMEM_DYN (NSTAGE * STAGE_WORDS * 4)   // 221184 bytes

template<bool RELU, bool RES, bool OUTH, bool SCALEQ>
__global__ void __launch_bounds__(256, 1)
gemm_mma(const __half* __restrict__ A, const __half* __restrict__ Bt,
         const float* __restrict__ bias, const float* __restrict__ res,
         void* __restrict__ Cv, int N, int K)
{
    extern __shared__ uint32_t smw[];
    const uint32_t sbase = smem_u32(smw);
    const int tid  = threadIdx.x;
    const int wid  = tid >> 5, lane = tid & 31;
    const int gq   = lane >> 2, tq = lane & 3;
    const int wm   = wid >> 2,  wn = wid & 3;
    const int m0   = blockIdx.y * BM, n0 = blockIdx.x * BN;
    const int nk   = K / BKH;

    float acc[4][8][4];
    #pragma unroll
    for (int i = 0; i < 4; i++)
        #pragma unroll
        for (int j = 0; j < 8; j++)
            #pragma unroll
            for (int q = 0; q < 4; q++) acc[i][j][q] = 0.f;

    const __half* Ag0 = A  + (size_t)m0 * K;
    const __half* Bg0 = Bt + (size_t)n0 * K;

    auto load_stage = [&](int s, int kt) {
        uint32_t sa = sbase + (uint32_t)s * (STAGE_WORDS * 4);
        const __half* Ag = Ag0 + kt * BKH;
        #pragma unroll
        for (int j = 0; j < 4; j++) {
            int c = tid + j * 256;
            int row = c >> 3, kc = c & 7;
            cp_async16(sa + (uint32_t)(row * 144 + kc * 16),
                       Ag + (size_t)row * K + kc * 8);
        }
        uint32_t sb = sa + A_WORDS * 4;
        const __half* Bg = Bg0 + kt * BKH;
        #pragma unroll
        for (int j = 0; j < 8; j++) {
            int c = tid + j * 256;
            int row = c >> 3, kc = c & 7;
            cp_async16(sb + (uint32_t)(row * 144 + kc * 16),
                       Bg + (size_t)row * K + kc * 8);
        }
        CP_COMMIT();
    };

    load_stage(0, 0);
    load_stage(1, 1);
    load_stage(2, 2);

    for (int kt = 0; kt < nk; kt++) {
        if (kt + 2 < nk) cp_wait<2>();
        else if (kt + 1 < nk) cp_wait<1>();
        else cp_wait<0>();
        __syncthreads();
        // Single barrier per iteration (see round-15 proof).
        if (kt + 3 < nk) load_stage((kt + 3) % NSTAGE, kt + 3);

        const uint32_t* a_s = smw + (kt % NSTAGE) * STAGE_WORDS;
        const uint32_t* b_s = a_s + A_WORDS;

        #pragma unroll
        for (int s = 0; s < 4; s++) {
            const int k8w = s * 8;
            uint32_t af[4][4];
            #pragma unroll
            for (int mi = 0; mi < 4; mi++) {
                int rb = wm * 64 + mi * 16;
                af[mi][0] = a_s[(rb + gq)     * PW + k8w + tq];
                af[mi][1] = a_s[(rb + gq + 8) * PW + k8w + tq];
                af[mi][2] = a_s[(rb + gq)     * PW + k8w + tq + 4];
                af[mi][3] = a_s[(rb + gq + 8) * PW + k8w + tq + 4];
            }
            uint32_t bf[8][2];
            #pragma unroll
            for (int ni = 0; ni < 8; ni++) {
                int nb = wn * 64 + ni * 8;
                bf[ni][0] = b_s[(nb + gq) * PW + k8w + tq];
                bf[ni][1] = b_s[(nb + gq) * PW + k8w + tq + 4];
            }
            #pragma unroll
            for (int mi = 0; mi < 4; mi++)
                #pragma unroll
                for (int ni = 0; ni < 8; ni++)
                    mma_f16(acc[mi][ni], af[mi], bf[ni]);
        }
    }

    // ---------- epilogue ----------
    const float qs = (SCALEQ && n0 < EMBED) ? SOFTMAX_C : 1.0f;
    float*  Cf = (float*)Cv;
    __half* Ch = (__half*)Cv;
    #pragma unroll
    for (int ni = 0; ni < 8; ni++) {
        int col = n0 + wn * 64 + ni * 8 + 2 * tq;
        float2 bv = __ldg((const float2*)(bias + col));
        #pragma unroll
        for (int mi = 0; mi < 4; mi++) {
            int row = m0 + wm * 64 + mi * 16 + gq;
            float2 v0, v1;
            v0.x = acc[mi][ni][0] + bv.x;
            v0.y = acc[mi][ni][1] + bv.y;
            v1.x = acc[mi][ni][2] + bv.x;
            v1.y = acc[mi][ni][3] + bv.y;
            if (RES) {
                float2 r0 = __ldg((const float2*)(res + (size_t)row * N + col));
                float2 r1 = __ldg((const float2*)(res + (size_t)(row + 8) * N + col));
                v0.x += r0.x; v0.y += r0.y;
                v1.x += r1.x; v1.y += r1.y;
            }
            if (RELU) {
                v0.x = fmaxf(v0.x, 0.f); v0.y = fmaxf(v0.y, 0.f);
                v1.x = fmaxf(v1.x, 0.f); v1.y = fmaxf(v1.y, 0.f);
            }
            if (SCALEQ) {
                v0.x *= qs; v0.y *= qs;
                v1.x *= qs; v1.y *= qs;
            }
            if (OUTH) {
                *(__half2*)(Ch + (size_t)row * N + col)       = __floats2half2_rn(v0.x, v0.y);
                *(__half2*)(Ch + (size_t)(row + 8) * N + col) = __floats2half2_rn(v1.x, v1.y);
            } else {
                *(float2*)(Cf + (size_t)row * N + col)       = v0;
                *(float2*)(Cf + (size_t)(row + 8) * N + col) = v1;
            }
        }
    }
}

// ---------------- weight transpose + fp16 round: in[K,N] -> out[N,K] ------
__global__ void transpose_h(const float* __restrict__ in, __half* __restrict__ out,
                            int K, int N)
{
    __shared__ float t[32][33];
    int n  = blockIdx.x * 32 + threadIdx.x;
    int k0 = blockIdx.y * 32;
    #pragma unroll
    for (int r = 0; r < 32; r += 8)
        t[threadIdx.y + r][threadIdx.x] = in[(size_t)(k0 + threadIdx.y + r) * N + n];
    __syncthreads();
    int k   = k0 + threadIdx.x;
    int nn0 = blockIdx.x * 32;
    #pragma unroll
    for (int r = 0; r < 32; r += 8)
        out[(size_t)(nn0 + threadIdx.y + r) * K + k] = __float2half_rn(t[threadIdx.x][threadIdx.y + r]);
}

// ---------------- LayerNorm: warp-per-row (no barriers, no smem) ----------
// 8 warps/CTA -> 8 rows/CTA; each lane owns 8 float4 (32 elems of 1024).
__global__ void __launch_bounds__(256)
ln_kernel(const float* __restrict__ x,
          const float* __restrict__ g,
          const float* __restrict__ b,
          __half* __restrict__ out)
{
    const int row  = blockIdx.x * 8 + (threadIdx.x >> 5);
    const int lane = threadIdx.x & 31;

    const float4* xr = (const float4*)(x + (size_t)row * EMBED);
    float4 v[8];
    float s = 0.f, s2 = 0.f;
    #pragma unroll
    for (int i = 0; i < 8; i++) {
        v[i] = xr[lane + i * 32];
        s  += v[i].x + v[i].y + v[i].z + v[i].w;
        s2 += v[i].x*v[i].x + v[i].y*v[i].y + v[i].z*v[i].z + v[i].w*v[i].w;
    }
    #pragma unroll
    for (int off = 16; off > 0; off >>= 1) {
        s  += __shfl_xor_sync(0xffffffffu, s,  off);
        s2 += __shfl_xor_sync(0xffffffffu, s2, off);
    }
    const float mu   = s * (1.0f / EMBED);
    const float rstd = rsqrtf(s2 * (1.0f / EMBED) - mu * mu + 1e-5f);

    __half2* orow = (__half2*)(out + (size_t)row * EMBED);
    #pragma unroll
    for (int i = 0; i < 8; i++) {
        float4 gv = ((const float4*)g)[lane + i * 32];
        float4 bv = ((const float4*)b)[lane + i * 32];
        orow[2 * (lane + i * 32)]     = __floats2half2_rn((v[i].x - mu) * rstd * gv.x + bv.x,
                                                          (v[i].y - mu) * rstd * gv.y + bv.y);
        orow[2 * (lane + i * 32) + 1] = __floats2half2_rn((v[i].z - mu) * rstd * gv.z + bv.z,
                                                          (v[i].w - mu) * rstd * gv.w + bv.w);
    }
}

// ---------------- flash attention via fp16 mma.sync (round-15 config) -----
// BQ=128 per CTA, 4 warps (32 q-rows: 2 x m16), BK=64, D=64, KV double-buffered,
// occupancy 2 (two independent CTAs/SM overlap softmax with MMA).
// P stays in registers (S C-frag == P@V A-frag). K B-frags via ldmatrix.x4.
#define AQW 0
#define AKW(b) (4608 + (b) * 2304)
#define AVW(b) (9216 + (b) * 2304)
#define ATT_SMEM (13824 * 4)        // 55296 bytes

__global__ void __launch_bounds__(128, 2)
attn_mma(const __half* __restrict__ qkv, __half* __restrict__ y)
{
    extern __shared__ uint32_t smw[];
    const uint32_t sbase = smem_u32(smw);

    const int qt = blockIdx.x, h = blockIdx.y, b = blockIdx.z;
    const int tid = threadIdx.x, wid = tid >> 5, lane = tid & 31;
    const int gq = lane >> 2, tq = lane & 3;
    const int rb0 = wid * 32;

    const __half* qbase = qkv + ((size_t)b * SEQ + qt * 128) * QKV3 + h * HDIM;
    const __half* kbase = qkv + (size_t)b * SEQ * QKV3 + EMBED + h * HDIM;
    const __half* vbase = kbase + EMBED;

    #pragma unroll
    for (int j = 0; j < 8; j++) {
        int c = tid + j * 128;
        int row = c >> 3, kc = c & 7;
        cp_async16(sbase + AQW * 4 + (uint32_t)(row * 144 + kc * 16),
                   qbase + (size_t)row * QKV3 + kc * 8);
    }
    #pragma unroll
    for (int j = 0; j < 4; j++) {
        int c = tid + j * 128;
        int row = c >> 3, kc = c & 7;
        cp_async16(sbase + AKW(0) * 4 + (uint32_t)(row * 144 + kc * 16),
                   kbase + (size_t)row * QKV3 + kc * 8);
        cp_async16(sbase + AVW(0) * 4 + (uint32_t)(row * 144 + kc * 16),
                   vbase + (size_t)row * QKV3 + kc * 8);
    }
    CP_COMMIT();

    float o[2][8][4];
    float mrow[2][2], lrow[2][2];
    #pragma unroll
    for (int mi = 0; mi < 2; mi++) {
        mrow[mi][0] = mrow[mi][1] = -1e30f;
        lrow[mi][0] = lrow[mi][1] = 0.f;
        #pragma unroll
        for (int ni = 0; ni < 8; ni++)
            #pragma unroll
            for (int q = 0; q < 4; q++) o[mi][ni][q] = 0.f;
    }

    cp_wait<0>();
    __syncthreads();

    uint32_t aq[4][2][4];
    {
        const uint32_t* q_s = smw + AQW;
        #pragma unroll
        for (int ks = 0; ks < 4; ks++) {
            const int k8w = ks * 8;
            #pragma unroll
            for (int mi = 0; mi < 2; mi++) {
                int rb = rb0 + mi * 16;
                aq[ks][mi][0] = q_s[(rb + gq)     * PW + k8w + tq];
                aq[ks][mi][1] = q_s[(rb + gq + 8) * PW + k8w + tq];
                aq[ks][mi][2] = q_s[(rb + gq)     * PW + k8w + tq + 4];
                aq[ks][mi][3] = q_s[(rb + gq + 8) * PW + k8w + tq + 4];
            }
        }
    }

    const int krow = ((lane >> 4) & 1) * 8 + (lane & 7);
    const int kwof = ((lane >> 3) & 1) * 4;
    const int vrow = ((lane >> 3) & 1) * 8 + (lane & 7);
    const int vcol = (lane >> 4) * 8;

    const int NT = SEQ / 64;
    for (int kt = 0; kt < NT; kt++) {
        const int cur = kt & 1;
        if (kt > 0) {
            cp_wait<0>();
            __syncthreads();
        }
        if (kt + 1 < NT) {
            const int nxt = cur ^ 1;
            #pragma unroll
            for (int j = 0; j < 4; j++) {
                int c = tid + j * 128;
                int row = c >> 3, kc = c & 7;
                cp_async16(sbase + AKW(nxt) * 4 + (uint32_t)(row * 144 + kc * 16),
                           kbase + (size_t)((kt + 1) * 64 + row) * QKV3 + kc * 8);
                cp_async16(sbase + AVW(nxt) * 4 + (uint32_t)(row * 144 + kc * 16),
                           vbase + (size_t)((kt + 1) * 64 + row) * QKV3 + kc * 8);
            }
            CP_COMMIT();
        }

        const uint32_t kb = sbase + AKW(cur) * 4;

        float s[2][8][4];
        #pragma unroll
        for (int mi = 0; mi < 2; mi++)
            #pragma unroll
            for (int ni = 0; ni < 8; ni++)
                #pragma unroll
                for (int q = 0; q < 4; q++) s[mi][ni][q] = 0.f;

        #pragma unroll
        for (int ks = 0; ks < 4; ks++) {
            const int k8w = ks * 8;
            uint32_t bk[8][2];
            #pragma unroll
            for (int j = 0; j < 4; j++) {
                uint32_t addr = kb + (uint32_t)(((16 * j + krow) * PW) + k8w + kwof) * 4;
                ldmatrix_x4(bk[2 * j][0], bk[2 * j][1],
                            bk[2 * j + 1][0], bk[2 * j + 1][1], addr);
            }
            #pragma unroll
            for (int mi = 0; mi < 2; mi++)
                #pragma unroll
                for (int ni = 0; ni < 8; ni++)
                    mma_f16(s[mi][ni], aq[ks][mi], bk[ni]);
        }

        uint32_t ph[2][8][2];
        #pragma unroll
        for (int mi = 0; mi < 2; mi++) {
            float rm0 = -1e30f, rm1 = -1e30f;
            #pragma unroll
            for (int ni = 0; ni < 8; ni++) {
                rm0 = fmaxf(rm0, fmaxf(s[mi][ni][0], s[mi][ni][1]));
                rm1 = fmaxf(rm1, fmaxf(s[mi][ni][2], s[mi][ni][3]));
            }
            rm0 = fmaxf(rm0, __shfl_xor_sync(0xffffffffu, rm0, 1));
            rm0 = fmaxf(rm0, __shfl_xor_sync(0xffffffffu, rm0, 2));
            rm1 = fmaxf(rm1, __shfl_xor_sync(0xffffffffu, rm1, 1));
            rm1 = fmaxf(rm1, __shfl_xor_sync(0xffffffffu, rm1, 2));

            float mn0 = fmaxf(mrow[mi][0], rm0);
            float mn1 = fmaxf(mrow[mi][1], rm1);
            float a0 = exp2_fast(mrow[mi][0] - mn0);
            float a1 = exp2_fast(mrow[mi][1] - mn1);
            mrow[mi][0] = mn0; mrow[mi][1] = mn1;

            float sum0 = 0.f, sum1 = 0.f;
            #pragma unroll
            for (int ni = 0; ni < 8; ni++) {
                float p0 = exp2_fast(s[mi][ni][0] - mn0);
                float p1 = exp2_fast(s[mi][ni][1] - mn0);
                float p2 = exp2_fast(s[mi][ni][2] - mn1);
                float p3 = exp2_fast(s[mi][ni][3] - mn1);
                sum0 += p0 + p1;
                sum1 += p2 + p3;
                __half2 hp0 = __floats2half2_rn(p0, p1);
                __half2 hp1 = __floats2half2_rn(p2, p3);
                ph[mi][ni][0] = *(uint32_t*)&hp0;
                ph[mi][ni][1] = *(uint32_t*)&hp1;
                o[mi][ni][0] *= a0; o[mi][ni][1] *= a0;
                o[mi][ni][2] *= a1; o[mi][ni][3] *= a1;
            }
            sum0 += __shfl_xor_sync(0xffffffffu, sum0, 1);
            sum0 += __shfl_xor_sync(0xffffffffu, sum0, 2);
            sum1 += __shfl_xor_sync(0xffffffffu, sum1, 1);
            sum1 += __shfl_xor_sync(0xffffffffu, sum1, 2);
            lrow[mi][0] = lrow[mi][0] * a0 + sum0;
            lrow[mi][1] = lrow[mi][1] * a1 + sum1;
        }

        const uint32_t vb = sbase + AVW(cur) * 4;
        #pragma unroll
        for (int ks = 0; ks < 4; ks++) {
            uint32_t ap[2][4];
            #pragma unroll
            for (int mi = 0; mi < 2; mi++) {
                ap[mi][0] = ph[mi][2 * ks][0];
                ap[mi][1] = ph[mi][2 * ks][1];
                ap[mi][2] = ph[mi][2 * ks + 1][0];
                ap[mi][3] = ph[mi][2 * ks + 1][1];
            }
            uint32_t bv[8][2];
            #pragma unroll
            for (int j = 0; j < 4; j++) {
                uint32_t addr = vb + (uint32_t)(((ks * 16 + vrow) * PH) + j * 16 + vcol) * 2;
                ldmatrix_x4_trans(bv[2 * j][0], bv[2 * j][1],
                                  bv[2 * j + 1][0], bv[2 * j + 1][1], addr);
            }
            #pragma unroll
            for (int mi = 0; mi < 2; mi++)
                #pragma unroll
                for (int ni = 0; ni < 8; ni++)
                    mma_f16(o[mi][ni], ap[mi], bv[ni]);
        }
    }

    #pragma unroll
    for (int mi = 0; mi < 2; mi++) {
        float inv0 = 1.0f / lrow[mi][0];
        float inv1 = 1.0f / lrow[mi][1];
        int r0 = qt * 128 + rb0 + mi * 16 + gq;
        #pragma unroll
        for (int ni = 0; ni < 8; ni++) {
            int col = h * HDIM + ni * 8 + 2 * tq;
            *(__half2*)(y + ((size_t)b * SEQ + r0) * EMBED + col) =
                __floats2half2_rn(o[mi][ni][0] * inv0, o[mi][ni][1] * inv0);
            *(__half2*)(y + ((size_t)b * SEQ + r0 + 8) * EMBED + col) =
                __floats2half2_rn(o[mi][ni][2] * inv1, o[mi][ni][3] * inv1);
        }
    }
}

// ---------------- launch (round-10/12 topology: known good) ----------------
extern "C" void kernel_launch(void* const* d_in, const int* in_sizes, int n_in,
                              void* d_out, int out_size)
{
    (void)in_sizes; (void)n_in; (void)out_size;
    const float* x      = (const float*)d_in[0];
    const float* ln1_g  = (const float*)d_in[1];
    const float* ln1_b  = (const float*)d_in[2];
    const float* w_qkv  = (const float*)d_in[3];
    const float* b_qkv  = (const float*)d_in[4];
    const float* w_out  = (const float*)d_in[5];
    const float* b_out  = (const float*)d_in[6];
    const float* ln2_g  = (const float*)d_in[7];
    const float* ln2_b  = (const float*)d_in[8];
    const float* w_up   = (const float*)d_in[9];
    const float* b_up   = (const float*)d_in[10];
    const float* w_down = (const float*)d_in[11];
    const float* b_down = (const float*)d_in[12];
    float* out = (float*)d_out;

    __half *p_ln, *p_qkv, *p_y, *p_h;
    float *p_x1;
    __half *p_wqkvT, *p_woutT, *p_wupT, *p_wdownT;
    cudaGetSymbolAddress((void**)&p_ln,     g_ln);
    cudaGetSymbolAddress((void**)&p_qkv,    g_qkv);
    cudaGetSymbolAddress((void**)&p_y,      g_y);
    cudaGetSymbolAddress((void**)&p_x1,     g_x1);
    cudaGetSymbolAddress((void**)&p_h,      g_h);
    cudaGetSymbolAddress((void**)&p_wqkvT,  g_wqkvT);
    cudaGetSymbolAddress((void**)&p_woutT,  g_woutT);
    cudaGetSymbolAddress((void**)&p_wupT,   g_wupT);
    cudaGetSymbolAddress((void**)&p_wdownT, g_wdownT);

    cudaFuncSetAttribute(gemm_mma<false, false, true, true>,
                         cudaFuncAttributeMaxDynamicSharedMemorySize, SMEM_DYN);
    cudaFuncSetAttribute(gemm_mma<false, true, false, false>,
                         cudaFuncAttributeMaxDynamicSharedMemorySize, SMEM_DYN);
    cudaFuncSetAttribute(gemm_mma<true, false, true, false>,
                         cudaFuncAttributeMaxDynamicSharedMemorySize, SMEM_DYN);
    cudaFuncSetAttribute(attn_mma,
                         cudaFuncAttributeMaxDynamicSharedMemorySize, ATT_SMEM);

    dim3 tb(32, 8);
    // 1) w_qkv transpose (needed by qkv GEMM) — main stream
    transpose_h<<<dim3(QKV3 / 32, EMBED / 32),  tb>>>(w_qkv,  p_wqkvT,  EMBED, QKV3);
    // 2) ln1 (fp16 out; warp-per-row)
    ln_kernel<<<NTOK / 8, 256>>>(x, ln1_g, ln1_b, p_ln);

    // fork: remaining weight transposes run concurrently with qkv GEMM + attention
    cudaEventRecord(g_aux.evf, 0);
    cudaStreamWaitEvent(g_aux.s2, g_aux.evf, 0);
    transpose_h<<<dim3(EMBED / 32, EMBED / 32), tb, 0, g_aux.s2>>>(w_out,  p_woutT,  EMBED, EMBED);
    transpose_h<<<dim3(HIDDEN / 32, EMBED / 32),tb, 0, g_aux.s2>>>(w_up,   p_wupT,   EMBED, HIDDEN);
    transpose_h<<<dim3(EMBED / 32, HIDDEN / 32),tb, 0, g_aux.s2>>>(w_down, p_wdownT, HIDDEN, EMBED);
    cudaEventRecord(g_aux.evj, g_aux.s2);

    // qkv = ln1 @ w_qkv + b_qkv  (fp16 out; q columns pre-scaled by SOFTMAX_C)
    gemm_mma<false, false, true, true><<<dim3(QKV3 / BN, NTOK / BM), 256, SMEM_DYN>>>(
        p_ln, p_wqkvT, b_qkv, nullptr, p_qkv, QKV3, EMBED);
    // attention (fp16 mma; BQ=128, occ 2; y fp16)
    attn_mma<<<dim3(SEQ / 128, HEADS, BATCH), 128, ATT_SMEM>>>(p_qkv, p_y);

    // join: transposed weights must be ready before out-proj / up / down
    cudaStreamWaitEvent(0, g_aux.evj, 0);

    // x1 = x + y @ w_out + b_out  (fp32 out)
    gemm_mma<false, true, false, false><<<dim3(EMBED / BN, NTOK / BM), 256, SMEM_DYN>>>(
        p_y, p_woutT, b_out, x, p_x1, EMBED, EMBED);
    // ln2 (fp16 out; warp-per-row)
    ln_kernel<<<NTOK / 8, 256>>>(p_x1, ln2_g, ln2_b, p_ln);
    // h = relu(ln2 @ w_up + b_up)  (fp16 out)
    gemm_mma<true, false, true, false><<<dim3(HIDDEN / BN, NTOK / BM), 256, SMEM_DYN>>>(
        p_ln, p_wupT, b_up, nullptr, p_h, HIDDEN, EMBED);
    // out = x1 + h @ w_down + b_down  (fp32 out)
    gemm_mma<false, true, false, false><<<dim3(EMBED / BN, NTOK / BM), 256, SMEM_DYN>>>(
        p_h, p_wdownT, b_down, p_x1, out, EMBED, HIDDEN);
}